// round 8
// baseline (speedup 1.0000x reference)
#include <cuda_runtime.h>
#include <stdint.h>

// ---------------- problem constants ----------------
#define C_IN   8
#define HW     256
#define M_OUT  8
#define P_OUT  254
#define PLANE  (P_OUT * P_OUT)

// ---------------- tiling ----------------
// 16-row strips; 10-row smem ring window; 2 sub-tiles of 8 rows per block.
#define STRIP_Y   16
#define RING_ROWS 10
#define CH_STRIDE 264                       // mod 32 == 8 -> conflict-free LDS
#define ROW_STRIDE (C_IN * CH_STRIDE)       // 2112 words per staged row
#define SMEM_WORDS (RING_ROWS * ROW_STRIDE) // 21120
#define SMEM_BYTES (SMEM_WORDS * 4)         // 84480

__device__ __forceinline__ uint32_t f2tf32(float f) {
    uint32_t r;
    asm("cvt.rna.tf32.f32 %0, %1;" : "=r"(r) : "f"(f));
    return r;
}

__device__ __forceinline__ void load_row(uint32_t* A, const uint32_t* p, int tig) {
    // 12 values: [ch2*6 + {0,1,2}=px+0..2, {3,4,5}=px+8..10]; ch = tig + ch2*4
    #pragma unroll
    for (int ch2 = 0; ch2 < 2; ch2++) {
        const uint32_t* q = p + (tig + ch2 * 4) * CH_STRIDE;
        A[ch2 * 6 + 0] = q[0];
        A[ch2 * 6 + 1] = q[1];
        A[ch2 * 6 + 2] = q[2];
        A[ch2 * 6 + 3] = q[8];
        A[ch2 * 6 + 4] = q[9];
        A[ch2 * 6 + 5] = q[10];
    }
}

__global__ __launch_bounds__(256, 2)
void conv_mma_kernel(const float* __restrict__ in,
                     const float* __restrict__ flt,
                     float* __restrict__ out) {
    extern __shared__ uint32_t sin_[];   // tf32 bits: ring of 10 rows [slot][c][px s264]

    const int tid  = threadIdx.x;
    const int w    = tid >> 5;
    const int lane = tid & 31;
    const int gid  = lane >> 2;       // 0..7 pixel group
    const int tig  = lane & 3;        // 0..3 channel group
    const int n    = blockIdx.y;
    const int y0   = blockIdx.x * STRIP_Y;

    const float* inb = in + (size_t)n * (C_IN * HW * HW);

    // ---- zero pad columns 256..263 for every (slot, ch); staging never writes them ----
    for (int i = tid; i < RING_ROWS * C_IN * 8; i += 256) {
        int slot = i >> 6;
        int c    = (i >> 3) & 7;
        sin_[slot * ROW_STRIDE + c * CH_STRIDE + 256 + (i & 7)] = 0u;
    }

    // ---- initial stage: strip rows 0..9 -> slots 0..9 ----
    #pragma unroll
    for (int it = 0; it < 20; it++) {
        int i   = tid + it * 256;     // 0..5119
        int row = i >> 9;             // 0..9
        int c   = (i >> 6) & 7;
        int x4  = i & 63;
        int gy  = y0 + row;
        float4 v = make_float4(0.f, 0.f, 0.f, 0.f);
        if (gy < HW) v = *(const float4*)(inb + (c * HW + gy) * HW + x4 * 4);
        uint4 t = make_uint4(f2tf32(v.x), f2tf32(v.y), f2tf32(v.z), f2tf32(v.w));
        *(uint4*)(sin_ + row * ROW_STRIDE + c * CH_STRIDE + x4 * 4) = t;
    }

    // ---- B fragments: b0 = W[m=gid][c=tig][r][s], b1 = W[gid][tig+4][r][s] ----
    uint32_t b0[9], b1[9];
    #pragma unroll
    for (int rs = 0; rs < 9; rs++) {
        int r = rs / 3, s = rs % 3;
        b0[rs] = f2tf32(flt[((gid * 8 + tig) * 3 + r) * 3 + s]);
        b1[rs] = f2tf32(flt[((gid * 8 + tig + 4) * 3 + r) * 3 + s]);
    }
    __syncthreads();

    #pragma unroll 1
    for (int sub = 0; sub < 2; sub++) {
        if (sub) {
            __syncthreads();   // prior sub's compute done reading slots 0..7
            // stage strip rows 10..17 -> slots 0..7
            #pragma unroll
            for (int it = 0; it < 16; it++) {
                int i   = tid + it * 256;   // 0..4095
                int j   = i >> 9;           // 0..7
                int c   = (i >> 6) & 7;
                int x4  = i & 63;
                int gy  = y0 + 10 + j;
                float4 v = make_float4(0.f, 0.f, 0.f, 0.f);
                if (gy < HW) v = *(const float4*)(inb + (c * HW + gy) * HW + x4 * 4);
                uint4 t = make_uint4(f2tf32(v.x), f2tf32(v.y), f2tf32(v.z), f2tf32(v.w));
                *(uint4*)(sin_ + j * ROW_STRIDE + c * CH_STRIDE + x4 * 4) = t;
            }
            __syncthreads();
        }

        // ring-slot offsets for window rows sub*8 + j, j=0..9
        int rowoff[10];
        #pragma unroll
        for (int j = 0; j < 10; j++) {
            int ra = sub * 8 + j;
            rowoff[j] = (ra >= 10 ? ra - 10 : ra) * ROW_STRIDE;
        }

        #pragma unroll 1
        for (int col = 0; col < 2; col++) {
            const int xb = (w + col * 8) * 16;
            const int g  = xb + gid;            // output px (group 0), <= 247
            const uint32_t* base = sin_ + g;

            uint32_t A[4][12];
            load_row(A[0], base + rowoff[0], tig);
            load_row(A[1], base + rowoff[1], tig);
            load_row(A[2], base + rowoff[2], tig);

            #pragma unroll
            for (int yi = 0; yi < 8; yi++) {
                if (yi < 7)   // prefetch one full iteration ahead
                    load_row(A[(yi + 3) & 3], base + rowoff[yi + 3], tig);

                float c0 = 0.f, c1 = 0.f, c2 = 0.f, c3 = 0.f;
                #pragma unroll
                for (int r = 0; r < 3; r++) {
                    const uint32_t* Ar = A[(yi + r) & 3];
                    #pragma unroll
                    for (int s = 0; s < 3; s++) {
                        const int rs = r * 3 + s;
                        asm volatile(
                            "mma.sync.aligned.m16n8k8.row.col.f32.tf32.tf32.f32 "
                            "{%0,%1,%2,%3}, {%4,%5,%6,%7}, {%8,%9}, {%0,%1,%2,%3};"
                            : "+f"(c0), "+f"(c1), "+f"(c2), "+f"(c3)
                            : "r"(Ar[s]), "r"(Ar[3 + s]), "r"(Ar[6 + s]), "r"(Ar[9 + s]),
                              "r"(b0[rs]), "r"(b1[rs]));
                    }
                }

                const int y = y0 + sub * 8 + yi;
                if (y < P_OUT) {
                    // C layout: c0:(px=g, m=2tig) c1:(g, 2tig+1) c2:(g+8, 2tig) c3:(g+8, 2tig+1)
                    float* ob = out + (size_t)(n * M_OUT) * PLANE + (size_t)y * P_OUT;
                    ob[(2 * tig    ) * PLANE + g] = c0;
                    ob[(2 * tig + 1) * PLANE + g] = c1;
                    if (g + 8 < P_OUT) {
                        ob[(2 * tig    ) * PLANE + g + 8] = c2;
                        ob[(2 * tig + 1) * PLANE + g + 8] = c3;
                    }
                }
            }
        }
    }
}

extern "C" void kernel_launch(void* const* d_in, const int* in_sizes, int n_in,
                              void* d_out, int out_size) {
    const float* in  = (const float*)d_in[0];   // (64, 8, 256, 256) fp32
    const float* flt = (const float*)d_in[1];   // (8, 8, 3, 3) fp32 OIHW
    float* out = (float*)d_out;                 // (64, 8, 254, 254) fp32

    (void)in_sizes; (void)n_in; (void)out_size;

    cudaFuncSetAttribute(conv_mma_kernel,
                         cudaFuncAttributeMaxDynamicSharedMemorySize, SMEM_BYTES);

    dim3 grid(16, 64);   // 16 strips of 16 rows x 64 batches
    conv_mma_kernel<<<grid, 256, SMEM_BYTES>>>(in, flt, out);
}

// round 10
// speedup vs baseline: 1.0661x; 1.0661x over previous
#include <cuda_runtime.h>
#include <stdint.h>

// ---------------- problem constants ----------------
#define C_IN   8
#define HW     256
#define M_OUT  8
#define P_OUT  254
#define PLANE  (P_OUT * P_OUT)

// ---------------- tiling ----------------
#define YB        8                         // output rows per block
#define ROWS_ST   (YB + 2)                  // staged input rows
#define CH_STRIDE 264                       // mod 32 == 8 -> conflict-free LDS
#define ROW_STRIDE (C_IN * CH_STRIDE)       // 2112 words per staged row
#define SMEM_WORDS (ROWS_ST * ROW_STRIDE)   // 21120
#define SMEM_BYTES (SMEM_WORDS * 4)         // 84480

__device__ __forceinline__ uint32_t f2tf32(float f) {
    uint32_t r;
    asm("cvt.rna.tf32.f32 %0, %1;" : "=r"(r) : "f"(f));
    return r;
}

__device__ __forceinline__ void load_row(uint32_t* A, const uint32_t* p, int tig) {
    // 12 values: [ch2*6 + {0,1,2}=px+0..2, {3,4,5}=px+8..10]; ch = tig + ch2*4
    #pragma unroll
    for (int ch2 = 0; ch2 < 2; ch2++) {
        const uint32_t* q = p + (tig + ch2 * 4) * CH_STRIDE;
        A[ch2 * 6 + 0] = q[0];
        A[ch2 * 6 + 1] = q[1];
        A[ch2 * 6 + 2] = q[2];
        A[ch2 * 6 + 3] = q[8];
        A[ch2 * 6 + 4] = q[9];
        A[ch2 * 6 + 5] = q[10];
    }
}

__global__ __launch_bounds__(256, 2)
void conv_mma_kernel(const float* __restrict__ in,
                     const float* __restrict__ flt,
                     float* __restrict__ out) {
    extern __shared__ uint32_t sin_[];   // tf32 bits: [row 0..9][c 0..7][px s264]

    const int tid  = threadIdx.x;
    const int w    = tid >> 5;
    const int lane = tid & 31;
    const int gid  = lane >> 2;       // 0..7 pixel group
    const int tig  = lane & 3;        // 0..3 channel group
    const int n    = blockIdx.y;
    const int y0   = blockIdx.x * YB;

    const float* inb = in + (size_t)n * (C_IN * HW * HW);

    // ---- stage input rows y0..y0+9 as TF32 bits (zero-fill OOB) ----
    #pragma unroll
    for (int it = 0; it < 20; it++) {
        int i   = tid + it * 256;     // 0..5119
        int row = i >> 9;             // 0..9
        int c   = (i >> 6) & 7;
        int x4  = i & 63;
        int gy  = y0 + row;
        float4 v = make_float4(0.f, 0.f, 0.f, 0.f);
        if (gy < HW) v = *(const float4*)(inb + (c * HW + gy) * HW + x4 * 4);
        uint4 t = make_uint4(f2tf32(v.x), f2tf32(v.y), f2tf32(v.z), f2tf32(v.w));
        *(uint4*)(sin_ + row * ROW_STRIDE + c * CH_STRIDE + x4 * 4) = t;
    }
    // zero pad columns 256..263 (ring loads touch px 256..257)
    for (int i = tid; i < ROWS_ST * C_IN * 8; i += 256) {
        int row = i >> 6;
        int c   = (i >> 3) & 7;
        sin_[row * ROW_STRIDE + c * CH_STRIDE + 256 + (i & 7)] = 0u;
    }

    // ---- B fragments: b0 = W[m=gid][c=tig][r][s], b1 = W[gid][tig+4][r][s] ----
    uint32_t b0[9], b1[9];
    #pragma unroll
    for (int rs = 0; rs < 9; rs++) {
        int r = rs / 3, s = rs % 3;
        b0[rs] = f2tf32(flt[((gid * 8 + tig) * 3 + r) * 3 + s]);
        b1[rs] = f2tf32(flt[((gid * 8 + tig + 4) * 3 + r) * 3 + s]);
    }
    __syncthreads();

    // ---- each warp: 2 x-columns of 16 px, sweep 8 y-rows, ring-4 A with prefetch ----
    #pragma unroll 1
    for (int col = 0; col < 2; col++) {
        const int xb = (w + col * 8) * 16;
        const int g  = xb + gid;            // output px (group 0), <= 247
        const uint32_t* base = sin_ + g;

        uint32_t A[4][12];
        load_row(A[0], base + 0 * ROW_STRIDE, tig);
        load_row(A[1], base + 1 * ROW_STRIDE, tig);
        load_row(A[2], base + 2 * ROW_STRIDE, tig);

        #pragma unroll
        for (int yi = 0; yi < YB; yi++) {
            if (yi < YB - 1)   // prefetch one iteration ahead (row yi+3, used at yi+1)
                load_row(A[(yi + 3) & 3], base + (yi + 3) * ROW_STRIDE, tig);

            // 3 independent accumulator chains, one per r
            float acc[3][4];
            #pragma unroll
            for (int r = 0; r < 3; r++)
                acc[r][0] = acc[r][1] = acc[r][2] = acc[r][3] = 0.f;

            #pragma unroll
            for (int s = 0; s < 3; s++) {
                #pragma unroll
                for (int r = 0; r < 3; r++) {     // consecutive MMAs -> different acc
                    const uint32_t* Ar = A[(yi + r) & 3];
                    const int rs = r * 3 + s;
                    asm volatile(
                        "mma.sync.aligned.m16n8k8.row.col.f32.tf32.tf32.f32 "
                        "{%0,%1,%2,%3}, {%4,%5,%6,%7}, {%8,%9}, {%0,%1,%2,%3};"
                        : "+f"(acc[r][0]), "+f"(acc[r][1]), "+f"(acc[r][2]), "+f"(acc[r][3])
                        : "r"(Ar[s]), "r"(Ar[3 + s]), "r"(Ar[6 + s]), "r"(Ar[9 + s]),
                          "r"(b0[rs]), "r"(b1[rs]));
                }
            }

            const int y = y0 + yi;
            if (y < P_OUT) {
                float c0 = acc[0][0] + acc[1][0] + acc[2][0];
                float c1 = acc[0][1] + acc[1][1] + acc[2][1];
                float c2 = acc[0][2] + acc[1][2] + acc[2][2];
                float c3 = acc[0][3] + acc[1][3] + acc[2][3];
                // C layout: c0:(px=g, m=2tig) c1:(g, 2tig+1) c2:(g+8, 2tig) c3:(g+8, 2tig+1)
                float* ob = out + (size_t)(n * M_OUT) * PLANE + (size_t)y * P_OUT;
                ob[(2 * tig    ) * PLANE + g] = c0;
                ob[(2 * tig + 1) * PLANE + g] = c1;
                if (g + 8 < P_OUT) {
                    ob[(2 * tig    ) * PLANE + g + 8] = c2;
                    ob[(2 * tig + 1) * PLANE + g + 8] = c3;
                }
            }
        }
    }
}

extern "C" void kernel_launch(void* const* d_in, const int* in_sizes, int n_in,
                              void* d_out, int out_size) {
    const float* in  = (const float*)d_in[0];   // (64, 8, 256, 256) fp32
    const float* flt = (const float*)d_in[1];   // (8, 8, 3, 3) fp32 OIHW
    float* out = (float*)d_out;                 // (64, 8, 254, 254) fp32

    (void)in_sizes; (void)n_in; (void)out_size;

    cudaFuncSetAttribute(conv_mma_kernel,
                         cudaFuncAttributeMaxDynamicSharedMemorySize, SMEM_BYTES);

    dim3 grid((P_OUT + YB - 1) / YB, 64);   // 32 y-blocks x 64 n
    conv_mma_kernel<<<grid, 256, SMEM_BYTES>>>(in, flt, out);
}